// round 14
// baseline (speedup 1.0000x reference)
#include <cuda_runtime.h>
#include <math.h>

#define SCALE_F 0.125f
#define EPS_F 1e-5f

// scratch (float offsets)
#define O_XT   0
#define O_QT   16384
#define O_KT   32768
#define O_VT   49152
#define O_ATT  65536
#define O_TMP  81920
#define O_QC   98304
#define O_CATT 114688
#define O_HID  131072
#define O_U    196608
#define O_SC   458752
#define O_AT   983040
#define O_CT   1245184
#define O_P    2293760
__device__ float g_buf[2818048];

__global__ void tin(const float* __restrict__ x, float* __restrict__ XT) {
    int i = blockIdx.x * 256 + threadIdx.x;
    if (i < 16384) XT[(i & 1023) * 16 + (i >> 10)] = x[i];
}

// Stage 1 partial GEMV. grid (N/32, ksplit), 256 thr = 32 ox * 8 kw.
// A is the sum of `aparts` buffers strided by astride.
__global__ void gemv_part(const float* __restrict__ A, int aparts, int astride,
                          const float* __restrict__ W, float* __restrict__ P,
                          int N, int K, int ksplit, int hs) {
    __shared__ float as[4096];
    const int tid = threadIdx.x, ox = tid & 31, kw = tid >> 5;
    const int klenB = K / ksplit;         // <= 256
    const int kl8 = klenB >> 3;
    const int kb0 = blockIdx.y * klenB;
    const int base = hs ? ((blockIdx.x * 32) >> 6) * hs : 0;

    for (int i = tid; i < klenB * 16; i += 256) {
        float s = 0.f;
        for (int p = 0; p < aparts; p++)
            s += __ldg(A + (size_t)p * astride + (size_t)(base + kb0) * 16 + i);
        as[i] = s;
    }
    __syncthreads();

    const int o = blockIdx.x * 32 + ox;
    float acc[16];
#pragma unroll
    for (int b = 0; b < 16; b++) acc[b] = 0.f;
    const float* Wp = W + (size_t)(kb0 + kw * kl8) * N + o;
    const float* ap = &as[kw * kl8 * 16];
#pragma unroll 8
    for (int kk = 0; kk < kl8; kk++) {
        float w = __ldg(Wp); Wp += N;
        const float4* a4 = (const float4*)(ap + kk * 16);
        float4 a0 = a4[0], a1 = a4[1], a2 = a4[2], a3 = a4[3];
        acc[0] += w * a0.x; acc[1] += w * a0.y; acc[2] += w * a0.z; acc[3] += w * a0.w;
        acc[4] += w * a1.x; acc[5] += w * a1.y; acc[6] += w * a1.z; acc[7] += w * a1.w;
        acc[8] += w * a2.x; acc[9] += w * a2.y; acc[10] += w * a2.z; acc[11] += w * a2.w;
        acc[12] += w * a3.x; acc[13] += w * a3.y; acc[14] += w * a3.z; acc[15] += w * a3.w;
    }
    __syncthreads();
    __shared__ float sr[8][32][17];
#pragma unroll
    for (int b = 0; b < 16; b++) sr[kw][ox][b] = acc[b];
    __syncthreads();
    for (int p = tid; p < 512; p += 256) {
        const int ol = p >> 4, b = p & 15;
        float s = 0.f;
#pragma unroll
        for (int g = 0; g < 8; g++) s += sr[g][ol][b];
        P[(size_t)blockIdx.y * N * 16 + (size_t)(blockIdx.x * 32 + ol) * 16 + b] = s;
    }
}

// Stage 2: sum ksplit partials + bias (+relu) (+resid)
__global__ void greduce(const float* __restrict__ P, const float* __restrict__ bias,
                        const float* __restrict__ resid, float* __restrict__ outT,
                        int N, int ksplit, int relu) {
    const int i = blockIdx.x * 256 + threadIdx.x;
    if (i >= N * 16) return;
    float s = 0.f;
    for (int g = 0; g < ksplit; g++) s += P[(size_t)g * N * 16 + i];
    float v = s + bias[i >> 4];
    if (relu) v = fmaxf(v, 0.f);
    if (resid) v += resid[i];
    outT[i] = v;
}

// self-attn scores: grid (16 b, 16 h, 4 tc), 128 thr. SCs[(b*16+h)*1024+t]
__global__ void sa_scores(const float* __restrict__ QT, const float* __restrict__ KT,
                          const float* __restrict__ kc, float* __restrict__ SCs) {
    const int b = blockIdx.x, h = blockIdx.y, tc = blockIdx.z, tid = threadIdx.x;
    __shared__ float q[64];
    if (tid < 64) q[tid] = QT[(h * 64 + tid) * 16 + b];
    __syncthreads();
    const size_t cbase = (size_t)(b * 16 + h) * 1023 * 64;
#pragma unroll
    for (int r = 0; r < 2; r++) {
        const int t = tc * 256 + r * 128 + tid;
        float a = 0.f;
        if (t < 1023) {
            const float4* kp = (const float4*)(kc + cbase + (size_t)t * 64);
            const float4* qp = (const float4*)q;
#pragma unroll
            for (int i = 0; i < 16; i++) {
                float4 kv = __ldg(kp + i), qv = qp[i];
                a += kv.x * qv.x + kv.y * qv.y + kv.z * qv.z + kv.w * qv.w;
            }
        } else {
            for (int j = 0; j < 64; j++) a += q[j] * KT[(h * 64 + j) * 16 + b];
        }
        SCs[(size_t)(b * 16 + h) * 1024 + t] = a * SCALE_F;
    }
}

// in-place softmax on rows of 1024: grid (16,16), 256 thr
__global__ void sa_softmax(float* __restrict__ SCs) {
    const int b = blockIdx.x, h = blockIdx.y, tid = threadIdx.x;
    float* p = SCs + (size_t)(b * 16 + h) * 1024;
    __shared__ float red[256];
    float v[4], m = -1e30f;
#pragma unroll
    for (int i = 0; i < 4; i++) { v[i] = p[tid + i * 256]; m = fmaxf(m, v[i]); }
    red[tid] = m; __syncthreads();
    for (int st = 128; st > 0; st >>= 1) { if (tid < st) red[tid] = fmaxf(red[tid], red[tid + st]); __syncthreads(); }
    m = red[0]; __syncthreads();
    float ssum = 0.f;
#pragma unroll
    for (int i = 0; i < 4; i++) { v[i] = __expf(v[i] - m); ssum += v[i]; }
    red[tid] = ssum; __syncthreads();
    for (int st = 128; st > 0; st >>= 1) { if (tid < st) red[tid] += red[tid + st]; __syncthreads(); }
    const float inv = 1.f / red[0];
#pragma unroll
    for (int i = 0; i < 4; i++) p[tid + i * 256] = v[i] * inv;
}

// V partials: grid (16 b, 16 h, 8 tc), 64 thr. VP[((b*16+h)*8+tc)*64+j]
__global__ void sa_v(const float* __restrict__ SCs, const float* __restrict__ VT,
                     const float* __restrict__ vc, float* __restrict__ VP) {
    const int b = blockIdx.x, h = blockIdx.y, tc = blockIdx.z, j = threadIdx.x;
    const size_t cbase = (size_t)(b * 16 + h) * 1023 * 64;
    const float* p = SCs + (size_t)(b * 16 + h) * 1024;
    float acc = 0.f;
    const int t0 = tc * 128;
#pragma unroll 8
    for (int i = 0; i < 128; i++) {
        const int t = t0 + i;
        float v = (t < 1023) ? __ldg(vc + cbase + (size_t)t * 64 + j)
                             : VT[(h * 64 + j) * 16 + b];
        acc += p[t] * v;
    }
    VP[(size_t)((b * 16 + h) * 8 + tc) * 64 + j] = acc;
}

// combine V partials -> ATT
__global__ void sa_comb(const float* __restrict__ VP, float* __restrict__ ATT) {
    const int b = blockIdx.x, h = blockIdx.y, j = threadIdx.x;
    float s = 0.f;
#pragma unroll
    for (int c = 0; c < 8; c++) s += VP[(size_t)((b * 16 + h) * 8 + c) * 64 + j];
    ATT[(h * 64 + j) * 16 + b] = s;
}

__global__ void lnk(const float* __restrict__ T, const float* __restrict__ g,
                    const float* __restrict__ be, float* __restrict__ XT) {
    const int b = blockIdx.x, tid = threadIdx.x;
    __shared__ float red[256];
    float s = 0.f;
    for (int o = tid; o < 1024; o += 256) s += T[o * 16 + b];
    red[tid] = s; __syncthreads();
    for (int st = 128; st > 0; st >>= 1) { if (tid < st) red[tid] += red[tid + st]; __syncthreads(); }
    const float mean = red[0] * (1.f / 1024.f);
    __syncthreads();
    float v = 0.f;
    for (int o = tid; o < 1024; o += 256) { float d = T[o * 16 + b] - mean; v += d * d; }
    red[tid] = v; __syncthreads();
    for (int st = 128; st > 0; st >>= 1) { if (tid < st) red[tid] += red[tid + st]; __syncthreads(); }
    const float rstd = rsqrtf(red[0] * (1.f / 1024.f) + EPS_F);
    for (int o = tid; o < 1024; o += 256)
        XT[o * 16 + b] = (T[o * 16 + b] - mean) * rstd * g[o] + be[o];
}

// U[(b*16+h)*1024+d] = sum_j Wk[d*1024 + h*64+j] * QC[(h*64+j)*16+b]
__global__ void ukern(const float* __restrict__ Wk, const float* __restrict__ QC,
                      float* __restrict__ U) {
    const int d = blockIdx.x, tid = threadIdx.x;
    __shared__ float w[1024];
    for (int i = tid; i < 1024; i += 256) w[i] = __ldg(&Wk[(size_t)d * 1024 + i]);
    __syncthreads();
    const int b = tid & 15, h = tid >> 4;
    float a = 0.f;
#pragma unroll 8
    for (int j = 0; j < 64; j++) a += w[h * 64 + j] * QC[(h * 64 + j) * 16 + b];
    U[(size_t)(b * 16 + h) * 1024 + d] = a;
}

// SCX[dh*262144 + (b*16+h)*1024+s] = partial dot over 512 d
__global__ void xscores(const float* __restrict__ enc, const float* __restrict__ U,
                        float* __restrict__ SCX) {
    const int b = blockIdx.x, s = blockIdx.y * 128 + threadIdx.x, dh = blockIdx.z;
    __shared__ float ush[16][512];
    float acc[16];
#pragma unroll
    for (int h = 0; h < 16; h++) acc[h] = 0.f;
    for (int i = threadIdx.x; i < 8192; i += 128)
        ush[i >> 9][i & 511] = __ldg(&U[(size_t)(b * 16 + (i >> 9)) * 1024 + dh * 512 + (i & 511)]);
    __syncthreads();
    const float* ep = enc + (size_t)(b * 1024 + s) * 1024 + dh * 512;
#pragma unroll 4
    for (int d = 0; d < 512; d += 4) {
        float4 e = __ldg((const float4*)(ep + d));
#pragma unroll
        for (int h = 0; h < 16; h++) {
            float4 u4 = *(const float4*)&ush[h][d];
            acc[h] += e.x * u4.x + e.y * u4.y + e.z * u4.z + e.w * u4.w;
        }
    }
#pragma unroll
    for (int h = 0; h < 16; h++)
        SCX[(size_t)dh * 262144 + (size_t)(b * 16 + h) * 1024 + s] = acc[h];
}

// sums 2 d-half partials, softmax, writes AT[(b*1024+s)*16+h]
__global__ void xsoftmax(const float* __restrict__ SCX, float* __restrict__ AT) {
    const int b = blockIdx.x, h = blockIdx.y, tid = threadIdx.x;
    const float* p0 = SCX + (size_t)(b * 16 + h) * 1024;
    const float* p1 = p0 + 262144;
    __shared__ float red[256];
    float v[4], m = -1e30f;
#pragma unroll
    for (int i = 0; i < 4; i++) {
        const int s = tid + i * 256;
        v[i] = SCALE_F * (p0[s] + p1[s]);
        m = fmaxf(m, v[i]);
    }
    red[tid] = m; __syncthreads();
    for (int st = 128; st > 0; st >>= 1) { if (tid < st) red[tid] = fmaxf(red[tid], red[tid + st]); __syncthreads(); }
    m = red[0]; __syncthreads();
    float ssum = 0.f;
#pragma unroll
    for (int i = 0; i < 4; i++) { v[i] = __expf(v[i] - m); ssum += v[i]; }
    red[tid] = ssum; __syncthreads();
    for (int st = 128; st > 0; st >>= 1) { if (tid < st) red[tid] += red[tid + st]; __syncthreads(); }
    const float inv = 1.f / red[0];
#pragma unroll
    for (int i = 0; i < 4; i++) AT[(size_t)(b * 1024 + tid + i * 256) * 16 + h] = v[i] * inv;
}

// ctx partials: grid (16 b, 4 dt, 4 sz), 256 thr. CT[sz*262144 + (h*1024+d)*16+b]
__global__ void xctx(const float* __restrict__ enc, const float* __restrict__ AT,
                     float* __restrict__ CT) {
    const int b = blockIdx.x, d = blockIdx.y * 256 + threadIdx.x, sz = blockIdx.z;
    const int s0 = sz * 256;
    float acc[16];
#pragma unroll
    for (int h = 0; h < 16; h++) acc[h] = 0.f;
    const float* ep = enc + (size_t)(b * 1024 + s0) * 1024 + d;
    const float4* ap = (const float4*)(AT + (size_t)(b * 1024 + s0) * 16);
#pragma unroll 4
    for (int s = 0; s < 256; s++) {
        float e = __ldg(ep); ep += 1024;
        float4 p0 = __ldg(ap), p1 = __ldg(ap + 1), p2 = __ldg(ap + 2), p3 = __ldg(ap + 3); ap += 4;
        acc[0] += e * p0.x; acc[1] += e * p0.y; acc[2] += e * p0.z; acc[3] += e * p0.w;
        acc[4] += e * p1.x; acc[5] += e * p1.y; acc[6] += e * p1.z; acc[7] += e * p1.w;
        acc[8] += e * p2.x; acc[9] += e * p2.y; acc[10] += e * p2.z; acc[11] += e * p2.w;
        acc[12] += e * p3.x; acc[13] += e * p3.y; acc[14] += e * p3.z; acc[15] += e * p3.w;
    }
#pragma unroll
    for (int h = 0; h < 16; h++)
        CT[(size_t)sz * 262144 + (size_t)(h * 1024 + d) * 16 + b] = acc[h];
}

__global__ void logits_k(const float* __restrict__ XT, const float* __restrict__ W,
                         const float* __restrict__ bias, float* __restrict__ out) {
    const int v = blockIdx.x, tid = threadIdx.x;
    float acc[16];
#pragma unroll
    for (int b = 0; b < 16; b++) acc[b] = 0.f;
    for (int k = tid; k < 1024; k += 256) {
        float w = __ldg(&W[k * 20 + v]);
        const float4* a4 = (const float4*)(XT + k * 16);
        float4 a0 = a4[0], a1 = a4[1], a2 = a4[2], a3 = a4[3];
        acc[0] += w * a0.x; acc[1] += w * a0.y; acc[2] += w * a0.z; acc[3] += w * a0.w;
        acc[4] += w * a1.x; acc[5] += w * a1.y; acc[6] += w * a1.z; acc[7] += w * a1.w;
        acc[8] += w * a2.x; acc[9] += w * a2.y; acc[10] += w * a2.z; acc[11] += w * a2.w;
        acc[12] += w * a3.x; acc[13] += w * a3.y; acc[14] += w * a3.z; acc[15] += w * a3.w;
    }
    __shared__ float sh[256][17];
#pragma unroll
    for (int b = 0; b < 16; b++) sh[tid][b] = acc[b];
    __syncthreads();
    for (int st = 128; st > 0; st >>= 1) {
        if (tid < st)
#pragma unroll
            for (int b = 0; b < 16; b++) sh[tid][b] += sh[tid + st][b];
        __syncthreads();
    }
    if (tid < 16) out[tid * 20 + v] = sh[0][tid] + bias[v];
}

static inline void gemv(const float* A, int aparts, int astride, const float* W,
                        const float* bias, const float* resid, float* P,
                        float* outT, int N, int K, int ksplit, int hs, int relu) {
    gemv_part<<<dim3(N / 32, ksplit), 256>>>(A, aparts, astride, W, P, N, K, ksplit, hs);
    greduce<<<N * 16 / 256, 256>>>(P, bias, resid, outT, N, ksplit, relu);
}

extern "C" void kernel_launch(void* const* d_in, const int* in_sizes, int n_in,
                              void* d_out, int out_size) {
    const float* x    = (const float*)d_in[0];
    const float* enc  = (const float*)d_in[1];
    const float* kc   = (const float*)d_in[2];
    const float* vc   = (const float*)d_in[3];
    const float* W[32]; for (int i = 4; i < 32; i++) W[i] = (const float*)d_in[i];
    void* bp; cudaGetSymbolAddress(&bp, g_buf);
    float* B = (float*)bp;
    float *XT = B + O_XT, *QT = B + O_QT, *KT = B + O_KT, *VT = B + O_VT;
    float *ATT = B + O_ATT, *TMP = B + O_TMP, *QC = B + O_QC, *CATT = B + O_CATT;
    float *HID = B + O_HID, *U = B + O_U, *SC = B + O_SC, *AT = B + O_AT;
    float *CT = B + O_CT, *P = B + O_P;

    tin<<<64, 256>>>(x, XT);
    for (int l = 0; l < 3; l++) {
        const size_t wo = (size_t)l * 1048576, bo = (size_t)l * 1024;
        const size_t co = (size_t)l * 16 * 16 * 1023 * 64;
        gemv(XT, 1, 0, W[4] + wo, W[5] + bo, nullptr, P, QT, 1024, 1024, 16, 0, 0);
        gemv(XT, 1, 0, W[6] + wo, W[7] + bo, nullptr, P, KT, 1024, 1024, 16, 0, 0);
        gemv(XT, 1, 0, W[8] + wo, W[9] + bo, nullptr, P, VT, 1024, 1024, 16, 0, 0);
        sa_scores<<<dim3(16, 16, 4), 128>>>(QT, KT, kc + co, SC);
        sa_softmax<<<dim3(16, 16), 256>>>(SC);
        sa_v<<<dim3(16, 16, 8), 64>>>(SC, VT, vc + co, AT);
        sa_comb<<<dim3(16, 16), 64>>>(AT, ATT);
        gemv(ATT, 1, 0, W[10] + wo, W[11] + bo, XT, P, TMP, 1024, 1024, 16, 0, 0);
        lnk<<<16, 256>>>(TMP, W[24] + bo, W[25] + bo, XT);
        gemv(XT, 1, 0, W[12] + wo, W[13] + bo, nullptr, P, QC, 1024, 1024, 16, 0, 0);
        ukern<<<1024, 256>>>(W[14] + wo, QC, U);
        xscores<<<dim3(16, 8, 2), 128>>>(enc, U, SC);
        xsoftmax<<<dim3(16, 16), 256>>>(SC, AT);
        xctx<<<dim3(16, 4, 4), 256>>>(enc, AT, CT);
        gemv(CT, 4, 262144, W[16] + wo, W[17] + bo, nullptr, P, CATT, 1024, 1024, 16, 1024, 0);
        gemv(CATT, 1, 0, W[18] + wo, W[19] + bo, XT, P, TMP, 1024, 1024, 16, 0, 0);
        lnk<<<16, 256>>>(TMP, W[26] + bo, W[27] + bo, XT);
        gemv(XT, 1, 0, W[20] + (size_t)l * 4194304, W[21] + (size_t)l * 4096,
             nullptr, P, HID, 4096, 1024, 4, 0, 1);
        gemv(HID, 1, 0, W[22] + (size_t)l * 4194304, W[23] + bo, XT, P, TMP,
             1024, 4096, 32, 0, 0);
        lnk<<<16, 256>>>(TMP, W[28] + bo, W[29] + bo, XT);
    }
    logits_k<<<20, 256>>>(XT, W[30], W[31], (float*)d_out);
}

// round 16
// speedup vs baseline: 1.2968x; 1.2968x over previous
#include <cuda_runtime.h>
#include <math.h>

#define SCALE_F 0.125f
#define EPS_F 1e-5f

// scratch (float offsets)
#define O_XT   0
#define O_QT   16384
#define O_KT   32768
#define O_VT   49152
#define O_ATT  65536
#define O_TMP  81920
#define O_QC   98304
#define O_CATT 114688
#define O_HID  131072
#define O_U    196608
#define O_SC   458752
#define O_AT   983040
#define O_CT   1245184
#define O_P    2293760
__device__ float g_buf[2818048];

__global__ void tin(const float* __restrict__ x, float* __restrict__ XT) {
    int i = blockIdx.x * 256 + threadIdx.x;
    if (i < 16384) XT[(i & 1023) * 16 + (i >> 10)] = x[i];
}

// Partial GEMV, 4 outputs/thread via float4 weight loads.
// grid (N/256, ksplit), 256 thr = 64 o-groups x 4 k-strips.
// A = sum of `aparts` buffers strided by astride. hs!=0: per-64-output head
// select, activation row base = head*hs.
__global__ void gemv_part4(const float* __restrict__ A, int aparts, int astride,
                           const float* __restrict__ W, float* __restrict__ P,
                           int N, int K, int ksplit, int hs) {
    __shared__ float as[2048];
    __shared__ float sr[4][64][21];
    const int tid = threadIdx.x, o4 = tid & 63, kw = tid >> 6;
    const int klenB = K / ksplit;        // <= 128
    const int kl = klenB >> 2;           // per-strip k count (>= 8)
    const int kb0 = blockIdx.y * klenB;
    const int hpb = hs ? 4 : 1;          // heads per block
    const int seg = klenB * 16;

    // stage activations (sum aparts), per head segment when hs
    for (int i = tid; i < hpb * seg; i += 256) {
        const int hl = i / seg, off = i - hl * seg;
        const size_t row = (size_t)(hs ? (blockIdx.x * 4 + hl) * hs : 0) + kb0 + (off >> 4);
        float s = 0.f;
        for (int p = 0; p < aparts; p++)
            s += __ldg(A + (size_t)p * astride + row * 16 + (off & 15));
        as[i] = s;
    }
    __syncthreads();

    const int o0 = blockIdx.x * 256 + o4 * 4;
    const float* ap = as + (hs ? (o4 >> 4) * seg : 0) + kw * kl * 16;
    const float* Wp = W + (size_t)(kb0 + kw * kl) * N + o0;
    float acc[4][16];
#pragma unroll
    for (int i = 0; i < 4; i++)
#pragma unroll
        for (int b = 0; b < 16; b++) acc[i][b] = 0.f;

#pragma unroll 4
    for (int kk = 0; kk < kl; kk++) {
        const float4 w4 = __ldg((const float4*)Wp); Wp += N;
        const float4* a4 = (const float4*)(ap + kk * 16);
        const float4 a0 = a4[0], a1 = a4[1], a2 = a4[2], a3 = a4[3];
        const float av[16] = {a0.x, a0.y, a0.z, a0.w, a1.x, a1.y, a1.z, a1.w,
                              a2.x, a2.y, a2.z, a2.w, a3.x, a3.y, a3.z, a3.w};
#pragma unroll
        for (int b = 0; b < 16; b++) {
            acc[0][b] += w4.x * av[b];
            acc[1][b] += w4.y * av[b];
            acc[2][b] += w4.z * av[b];
            acc[3][b] += w4.w * av[b];
        }
    }

    // in-block reduction over 4 k-strips, one output-round at a time
    for (int r = 0; r < 4; r++) {
        __syncthreads();
#pragma unroll
        for (int b = 0; b < 16; b++) sr[kw][o4][b] = acc[r][b];
        __syncthreads();
        for (int p = tid; p < 1024; p += 256) {
            const int ol = p >> 4, b = p & 15;
            const float s = sr[0][ol][b] + sr[1][ol][b] + sr[2][ol][b] + sr[3][ol][b];
            P[(size_t)blockIdx.y * N * 16 + (size_t)(blockIdx.x * 256 + ol * 4 + r) * 16 + b] = s;
        }
    }
}

// Stage 2: sum ksplit partials + bias (+relu) (+resid)
__global__ void greduce(const float* __restrict__ P, const float* __restrict__ bias,
                        const float* __restrict__ resid, float* __restrict__ outT,
                        int N, int ksplit, int relu) {
    const int i = blockIdx.x * 256 + threadIdx.x;
    if (i >= N * 16) return;
    float s = 0.f;
    for (int g = 0; g < ksplit; g++) s += P[(size_t)g * N * 16 + i];
    float v = s + bias[i >> 4];
    if (relu) v = fmaxf(v, 0.f);
    if (resid) v += resid[i];
    outT[i] = v;
}

// self-attn scores: grid (16 b, 16 h, 4 tc), 128 thr. SCs[(b*16+h)*1024+t]
__global__ void sa_scores(const float* __restrict__ QT, const float* __restrict__ KT,
                          const float* __restrict__ kc, float* __restrict__ SCs) {
    const int b = blockIdx.x, h = blockIdx.y, tc = blockIdx.z, tid = threadIdx.x;
    __shared__ float q[64];
    if (tid < 64) q[tid] = QT[(h * 64 + tid) * 16 + b];
    __syncthreads();
    const size_t cbase = (size_t)(b * 16 + h) * 1023 * 64;
#pragma unroll
    for (int r = 0; r < 2; r++) {
        const int t = tc * 256 + r * 128 + tid;
        float a = 0.f;
        if (t < 1023) {
            const float4* kp = (const float4*)(kc + cbase + (size_t)t * 64);
            const float4* qp = (const float4*)q;
#pragma unroll
            for (int i = 0; i < 16; i++) {
                float4 kv = __ldg(kp + i), qv = qp[i];
                a += kv.x * qv.x + kv.y * qv.y + kv.z * qv.z + kv.w * qv.w;
            }
        } else {
            for (int j = 0; j < 64; j++) a += q[j] * KT[(h * 64 + j) * 16 + b];
        }
        SCs[(size_t)(b * 16 + h) * 1024 + t] = a * SCALE_F;
    }
}

// in-place softmax on rows of 1024: grid (16,16), 256 thr
__global__ void sa_softmax(float* __restrict__ SCs) {
    const int b = blockIdx.x, h = blockIdx.y, tid = threadIdx.x;
    float* p = SCs + (size_t)(b * 16 + h) * 1024;
    __shared__ float red[256];
    float v[4], m = -1e30f;
#pragma unroll
    for (int i = 0; i < 4; i++) { v[i] = p[tid + i * 256]; m = fmaxf(m, v[i]); }
    red[tid] = m; __syncthreads();
    for (int st = 128; st > 0; st >>= 1) { if (tid < st) red[tid] = fmaxf(red[tid], red[tid + st]); __syncthreads(); }
    m = red[0]; __syncthreads();
    float ssum = 0.f;
#pragma unroll
    for (int i = 0; i < 4; i++) { v[i] = __expf(v[i] - m); ssum += v[i]; }
    red[tid] = ssum; __syncthreads();
    for (int st = 128; st > 0; st >>= 1) { if (tid < st) red[tid] += red[tid + st]; __syncthreads(); }
    const float inv = 1.f / red[0];
#pragma unroll
    for (int i = 0; i < 4; i++) p[tid + i * 256] = v[i] * inv;
}

// V partials: grid (16 b, 16 h, 8 tc), 64 thr. VP[((b*16+h)*8+tc)*64+j]
__global__ void sa_v(const float* __restrict__ SCs, const float* __restrict__ VT,
                     const float* __restrict__ vc, float* __restrict__ VP) {
    const int b = blockIdx.x, h = blockIdx.y, tc = blockIdx.z, j = threadIdx.x;
    const size_t cbase = (size_t)(b * 16 + h) * 1023 * 64;
    const float* p = SCs + (size_t)(b * 16 + h) * 1024;
    float acc = 0.f;
    const int t0 = tc * 128;
#pragma unroll 8
    for (int i = 0; i < 128; i++) {
        const int t = t0 + i;
        float v = (t < 1023) ? __ldg(vc + cbase + (size_t)t * 64 + j)
                             : VT[(h * 64 + j) * 16 + b];
        acc += p[t] * v;
    }
    VP[(size_t)((b * 16 + h) * 8 + tc) * 64 + j] = acc;
}

// combine V partials -> ATT
__global__ void sa_comb(const float* __restrict__ VP, float* __restrict__ ATT) {
    const int b = blockIdx.x, h = blockIdx.y, j = threadIdx.x;
    float s = 0.f;
#pragma unroll
    for (int c = 0; c < 8; c++) s += VP[(size_t)((b * 16 + h) * 8 + c) * 64 + j];
    ATT[(h * 64 + j) * 16 + b] = s;
}

__global__ void lnk(const float* __restrict__ T, const float* __restrict__ g,
                    const float* __restrict__ be, float* __restrict__ XT) {
    const int b = blockIdx.x, tid = threadIdx.x;
    __shared__ float red[256];
    float s = 0.f;
    for (int o = tid; o < 1024; o += 256) s += T[o * 16 + b];
    red[tid] = s; __syncthreads();
    for (int st = 128; st > 0; st >>= 1) { if (tid < st) red[tid] += red[tid + st]; __syncthreads(); }
    const float mean = red[0] * (1.f / 1024.f);
    __syncthreads();
    float v = 0.f;
    for (int o = tid; o < 1024; o += 256) { float d = T[o * 16 + b] - mean; v += d * d; }
    red[tid] = v; __syncthreads();
    for (int st = 128; st > 0; st >>= 1) { if (tid < st) red[tid] += red[tid + st]; __syncthreads(); }
    const float rstd = rsqrtf(red[0] * (1.f / 1024.f) + EPS_F);
    for (int o = tid; o < 1024; o += 256)
        XT[o * 16 + b] = (T[o * 16 + b] - mean) * rstd * g[o] + be[o];
}

// U[(b*16+h)*1024+d] = sum_j Wk[d*1024 + h*64+j] * QC[(h*64+j)*16+b]
__global__ void ukern(const float* __restrict__ Wk, const float* __restrict__ QC,
                      float* __restrict__ U) {
    const int d = blockIdx.x, tid = threadIdx.x;
    __shared__ float w[1024];
    for (int i = tid; i < 1024; i += 256) w[i] = __ldg(&Wk[(size_t)d * 1024 + i]);
    __syncthreads();
    const int b = tid & 15, h = tid >> 4;
    float a = 0.f;
#pragma unroll 8
    for (int j = 0; j < 64; j++) a += w[h * 64 + j] * QC[(h * 64 + j) * 16 + b];
    U[(size_t)(b * 16 + h) * 1024 + d] = a;
}

// SCX[dh*262144 + (b*16+h)*1024+s] = partial dot over 512 d
__global__ void xscores(const float* __restrict__ enc, const float* __restrict__ U,
                        float* __restrict__ SCX) {
    const int b = blockIdx.x, s = blockIdx.y * 128 + threadIdx.x, dh = blockIdx.z;
    __shared__ float ush[16][512];
    float acc[16];
#pragma unroll
    for (int h = 0; h < 16; h++) acc[h] = 0.f;
    for (int i = threadIdx.x; i < 8192; i += 128)
        ush[i >> 9][i & 511] = __ldg(&U[(size_t)(b * 16 + (i >> 9)) * 1024 + dh * 512 + (i & 511)]);
    __syncthreads();
    const float* ep = enc + (size_t)(b * 1024 + s) * 1024 + dh * 512;
#pragma unroll 4
    for (int d = 0; d < 512; d += 4) {
        float4 e = __ldg((const float4*)(ep + d));
#pragma unroll
        for (int h = 0; h < 16; h++) {
            float4 u4 = *(const float4*)&ush[h][d];
            acc[h] += e.x * u4.x + e.y * u4.y + e.z * u4.z + e.w * u4.w;
        }
    }
#pragma unroll
    for (int h = 0; h < 16; h++)
        SCX[(size_t)dh * 262144 + (size_t)(b * 16 + h) * 1024 + s] = acc[h];
}

// sums 2 d-half partials, softmax, writes AT[(b*1024+s)*16+h]
__global__ void xsoftmax(const float* __restrict__ SCX, float* __restrict__ AT) {
    const int b = blockIdx.x, h = blockIdx.y, tid = threadIdx.x;
    const float* p0 = SCX + (size_t)(b * 16 + h) * 1024;
    const float* p1 = p0 + 262144;
    __shared__ float red[256];
    float v[4], m = -1e30f;
#pragma unroll
    for (int i = 0; i < 4; i++) {
        const int s = tid + i * 256;
        v[i] = SCALE_F * (p0[s] + p1[s]);
        m = fmaxf(m, v[i]);
    }
    red[tid] = m; __syncthreads();
    for (int st = 128; st > 0; st >>= 1) { if (tid < st) red[tid] = fmaxf(red[tid], red[tid + st]); __syncthreads(); }
    m = red[0]; __syncthreads();
    float ssum = 0.f;
#pragma unroll
    for (int i = 0; i < 4; i++) { v[i] = __expf(v[i] - m); ssum += v[i]; }
    red[tid] = ssum; __syncthreads();
    for (int st = 128; st > 0; st >>= 1) { if (tid < st) red[tid] += red[tid + st]; __syncthreads(); }
    const float inv = 1.f / red[0];
#pragma unroll
    for (int i = 0; i < 4; i++) AT[(size_t)(b * 1024 + tid + i * 256) * 16 + h] = v[i] * inv;
}

// ctx partials: grid (16 b, 4 dt, 4 sz), 256 thr. CT[sz*262144 + (h*1024+d)*16+b]
__global__ void xctx(const float* __restrict__ enc, const float* __restrict__ AT,
                     float* __restrict__ CT) {
    const int b = blockIdx.x, d = blockIdx.y * 256 + threadIdx.x, sz = blockIdx.z;
    const int s0 = sz * 256;
    float acc[16];
#pragma unroll
    for (int h = 0; h < 16; h++) acc[h] = 0.f;
    const float* ep = enc + (size_t)(b * 1024 + s0) * 1024 + d;
    const float4* ap = (const float4*)(AT + (size_t)(b * 1024 + s0) * 16);
#pragma unroll 4
    for (int s = 0; s < 256; s++) {
        float e = __ldg(ep); ep += 1024;
        float4 p0 = __ldg(ap), p1 = __ldg(ap + 1), p2 = __ldg(ap + 2), p3 = __ldg(ap + 3); ap += 4;
        acc[0] += e * p0.x; acc[1] += e * p0.y; acc[2] += e * p0.z; acc[3] += e * p0.w;
        acc[4] += e * p1.x; acc[5] += e * p1.y; acc[6] += e * p1.z; acc[7] += e * p1.w;
        acc[8] += e * p2.x; acc[9] += e * p2.y; acc[10] += e * p2.z; acc[11] += e * p2.w;
        acc[12] += e * p3.x; acc[13] += e * p3.y; acc[14] += e * p3.z; acc[15] += e * p3.w;
    }
#pragma unroll
    for (int h = 0; h < 16; h++)
        CT[(size_t)sz * 262144 + (size_t)(h * 1024 + d) * 16 + b] = acc[h];
}

__global__ void logits_k(const float* __restrict__ XT, const float* __restrict__ W,
                         const float* __restrict__ bias, float* __restrict__ out) {
    const int v = blockIdx.x, tid = threadIdx.x;
    float acc[16];
#pragma unroll
    for (int b = 0; b < 16; b++) acc[b] = 0.f;
    for (int k = tid; k < 1024; k += 256) {
        float w = __ldg(&W[k * 20 + v]);
        const float4* a4 = (const float4*)(XT + k * 16);
        float4 a0 = a4[0], a1 = a4[1], a2 = a4[2], a3 = a4[3];
        acc[0] += w * a0.x; acc[1] += w * a0.y; acc[2] += w * a0.z; acc[3] += w * a0.w;
        acc[4] += w * a1.x; acc[5] += w * a1.y; acc[6] += w * a1.z; acc[7] += w * a1.w;
        acc[8] += w * a2.x; acc[9] += w * a2.y; acc[10] += w * a2.z; acc[11] += w * a2.w;
        acc[12] += w * a3.x; acc[13] += w * a3.y; acc[14] += w * a3.z; acc[15] += w * a3.w;
    }
    __shared__ float sh[256][17];
#pragma unroll
    for (int b = 0; b < 16; b++) sh[tid][b] = acc[b];
    __syncthreads();
    for (int st = 128; st > 0; st >>= 1) {
        if (tid < st)
#pragma unroll
            for (int b = 0; b < 16; b++) sh[tid][b] += sh[tid + st][b];
        __syncthreads();
    }
    if (tid < 16) out[tid * 20 + v] = sh[0][tid] + bias[v];
}

static inline void gemv(const float* A, int aparts, int astride, const float* W,
                        const float* bias, const float* resid, float* P,
                        float* outT, int N, int K, int ksplit, int hs, int relu) {
    gemv_part4<<<dim3(N / 256, ksplit), 256>>>(A, aparts, astride, W, P, N, K, ksplit, hs);
    greduce<<<N * 16 / 256, 256>>>(P, bias, resid, outT, N, ksplit, relu);
}

extern "C" void kernel_launch(void* const* d_in, const int* in_sizes, int n_in,
                              void* d_out, int out_size) {
    const float* x    = (const float*)d_in[0];
    const float* enc  = (const float*)d_in[1];
    const float* kc   = (const float*)d_in[2];
    const float* vc   = (const float*)d_in[3];
    const float* W[32]; for (int i = 4; i < 32; i++) W[i] = (const float*)d_in[i];
    void* bp; cudaGetSymbolAddress(&bp, g_buf);
    float* B = (float*)bp;
    float *XT = B + O_XT, *QT = B + O_QT, *KT = B + O_KT, *VT = B + O_VT;
    float *ATT = B + O_ATT, *TMP = B + O_TMP, *QC = B + O_QC, *CATT = B + O_CATT;
    float *HID = B + O_HID, *U = B + O_U, *SC = B + O_SC, *AT = B + O_AT;
    float *CT = B + O_CT, *P = B + O_P;

    tin<<<64, 256>>>(x, XT);
    for (int l = 0; l < 3; l++) {
        const size_t wo = (size_t)l * 1048576, bo = (size_t)l * 1024;
        const size_t co = (size_t)l * 16 * 16 * 1023 * 64;
        gemv(XT, 1, 0, W[4] + wo, W[5] + bo, nullptr, P, QT, 1024, 1024, 32, 0, 0);
        gemv(XT, 1, 0, W[6] + wo, W[7] + bo, nullptr, P, KT, 1024, 1024, 32, 0, 0);
        gemv(XT, 1, 0, W[8] + wo, W[9] + bo, nullptr, P, VT, 1024, 1024, 32, 0, 0);
        sa_scores<<<dim3(16, 16, 4), 128>>>(QT, KT, kc + co, SC);
        sa_softmax<<<dim3(16, 16), 256>>>(SC);
        sa_v<<<dim3(16, 16, 8), 64>>>(SC, VT, vc + co, AT);
        sa_comb<<<dim3(16, 16), 64>>>(AT, ATT);
        gemv(ATT, 1, 0, W[10] + wo, W[11] + bo, XT, P, TMP, 1024, 1024, 32, 0, 0);
        lnk<<<16, 256>>>(TMP, W[24] + bo, W[25] + bo, XT);
        gemv(XT, 1, 0, W[12] + wo, W[13] + bo, nullptr, P, QC, 1024, 1024, 32, 0, 0);
        ukern<<<1024, 256>>>(W[14] + wo, QC, U);
        xscores<<<dim3(16, 8, 2), 128>>>(enc, U, SC);
        xsoftmax<<<dim3(16, 16), 256>>>(SC, AT);
        xctx<<<dim3(16, 4, 4), 256>>>(enc, AT, CT);
        gemv(CT, 4, 262144, W[16] + wo, W[17] + bo, nullptr, P, CATT, 1024, 1024, 32, 1024, 0);
        gemv(CATT, 1, 0, W[18] + wo, W[19] + bo, XT, P, TMP, 1024, 1024, 32, 0, 0);
        lnk<<<16, 256>>>(TMP, W[26] + bo, W[27] + bo, XT);
        gemv(XT, 1, 0, W[20] + (size_t)l * 4194304, W[21] + (size_t)l * 4096,
             nullptr, P, HID, 4096, 1024, 8, 0, 1);
        gemv(HID, 1, 0, W[22] + (size_t)l * 4194304, W[23] + bo, XT, P, TMP,
             1024, 4096, 32, 0, 0);
        lnk<<<16, 256>>>(TMP, W[28] + bo, W[29] + bo, XT);
    }
    logits_k<<<20, 256>>>(XT, W[30], W[31], (float*)d_out);
}

// round 17
// speedup vs baseline: 1.4361x; 1.1075x over previous
#include <cuda_runtime.h>
#include <math.h>

#define SCALE_F 0.125f
#define EPS_F 1e-5f

// scratch (float offsets)
#define O_XT   0
#define O_QT   16384
#define O_KT   32768
#define O_VT   49152
#define O_ATT  65536
#define O_TMP  81920
#define O_QC   98304
#define O_CATT 114688
#define O_HID  131072
#define O_U    196608
#define O_SC   458752
#define O_AT   983040
#define O_CT   1245184
#define O_P    2293760
__device__ float g_buf[3870720];

__global__ void tin(const float* __restrict__ x, float* __restrict__ XT) {
    int i = blockIdx.x * 256 + threadIdx.x;
    if (i < 16384) XT[(i & 1023) * 16 + (i >> 10)] = x[i];
}

// Partial GEMV, 2 outputs/thread, float2 weight loads.
// grid (N/128, ksplit, nw). blockIdx.z selects W0/W1/W2; partials at
// P + z*ksplit*N*16. A = sum of `aparts` buffers strided astride.
// hs!=0: per-64-output head select (block covers 2 heads).
__global__ void __launch_bounds__(256, 3)
gemv_part2(const float* __restrict__ A, int aparts, int astride,
           const float* __restrict__ W0, const float* __restrict__ W1,
           const float* __restrict__ W2, float* __restrict__ P,
           int N, int K, int ksplit, int hs) {
    __shared__ float as[2048];
    __shared__ float sr[4][64][17];
    const int tid = threadIdx.x, o2 = tid & 63, kw = tid >> 6;
    const int klenB = K / ksplit;        // <= 128
    const int kl = klenB >> 2;           // per-strip k count (>= 8)
    const int kb0 = blockIdx.y * klenB;
    const int hpb = hs ? 2 : 1;
    const int seg = klenB * 16;
    const float* W = (blockIdx.z == 0) ? W0 : ((blockIdx.z == 1) ? W1 : W2);

    for (int i = tid; i < hpb * seg; i += 256) {
        const int hl = i / seg, off = i - hl * seg;
        const size_t row = (size_t)(hs ? (blockIdx.x * 2 + hl) * hs : 0) + kb0 + (off >> 4);
        float s = 0.f;
        for (int p = 0; p < aparts; p++)
            s += __ldg(A + (size_t)p * astride + row * 16 + (off & 15));
        as[i] = s;
    }
    __syncthreads();

    const int o0 = blockIdx.x * 128 + o2 * 2;
    const float* ap = as + (hs ? (o2 >> 5) * seg : 0) + kw * kl * 16;
    const float* Wp = W + (size_t)(kb0 + kw * kl) * N + o0;
    float acc[2][16];
#pragma unroll
    for (int i = 0; i < 2; i++)
#pragma unroll
        for (int b = 0; b < 16; b++) acc[i][b] = 0.f;

#pragma unroll 8
    for (int kk = 0; kk < kl; kk++) {
        const float2 w2 = __ldg((const float2*)Wp); Wp += N;
        const float4* a4 = (const float4*)(ap + kk * 16);
        const float4 a0 = a4[0], a1 = a4[1], a2 = a4[2], a3 = a4[3];
        const float av[16] = {a0.x, a0.y, a0.z, a0.w, a1.x, a1.y, a1.z, a1.w,
                              a2.x, a2.y, a2.z, a2.w, a3.x, a3.y, a3.z, a3.w};
#pragma unroll
        for (int b = 0; b < 16; b++) {
            acc[0][b] += w2.x * av[b];
            acc[1][b] += w2.y * av[b];
        }
    }

    float* Pz = P + (size_t)blockIdx.z * ksplit * N * 16 + (size_t)blockIdx.y * N * 16;
    for (int r = 0; r < 2; r++) {
        __syncthreads();
#pragma unroll
        for (int b = 0; b < 16; b++) sr[kw][o2][b] = acc[r][b];
        __syncthreads();
        for (int p = tid; p < 1024; p += 256) {
            const int ol = p >> 4, b = p & 15;
            const float s = sr[0][ol][b] + sr[1][ol][b] + sr[2][ol][b] + sr[3][ol][b];
            Pz[(size_t)(blockIdx.x * 128 + ol * 2 + r) * 16 + b] = s;
        }
    }
}

// sum ksplit partials + bias (+relu) (+resid)
__global__ void greduce(const float* __restrict__ P, const float* __restrict__ bias,
                        const float* __restrict__ resid, float* __restrict__ outT,
                        int N, int ksplit, int relu) {
    const int i = blockIdx.x * 256 + threadIdx.x;
    if (i >= N * 16) return;
    float s = 0.f;
    for (int g = 0; g < ksplit; g++) s += P[(size_t)g * N * 16 + i];
    float v = s + bias[i >> 4];
    if (relu) v = fmaxf(v, 0.f);
    if (resid) v += resid[i];
    outT[i] = v;
}

// fused reduce for the QKV triple launch: grid (N*16/256, 3)
__global__ void greduce3(const float* __restrict__ P,
                         const float* __restrict__ b0, const float* __restrict__ b1,
                         const float* __restrict__ b2, float* __restrict__ o0,
                         float* __restrict__ o1, float* __restrict__ o2,
                         int N, int ksplit) {
    const int z = blockIdx.y;
    const float* bias = (z == 0) ? b0 : ((z == 1) ? b1 : b2);
    float* outT = (z == 0) ? o0 : ((z == 1) ? o1 : o2);
    const float* Pz = P + (size_t)z * ksplit * N * 16;
    const int i = blockIdx.x * 256 + threadIdx.x;
    if (i >= N * 16) return;
    float s = 0.f;
    for (int g = 0; g < ksplit; g++) s += Pz[(size_t)g * N * 16 + i];
    outT[i] = s + bias[i >> 4];
}

// self-attn scores: grid (16 b, 16 h, 4 tc), 128 thr. SCs[(b*16+h)*1024+t]
__global__ void sa_scores(const float* __restrict__ QT, const float* __restrict__ KT,
                          const float* __restrict__ kc, float* __restrict__ SCs) {
    const int b = blockIdx.x, h = blockIdx.y, tc = blockIdx.z, tid = threadIdx.x;
    __shared__ float q[64];
    if (tid < 64) q[tid] = QT[(h * 64 + tid) * 16 + b];
    __syncthreads();
    const size_t cbase = (size_t)(b * 16 + h) * 1023 * 64;
#pragma unroll
    for (int r = 0; r < 2; r++) {
        const int t = tc * 256 + r * 128 + tid;
        float a = 0.f;
        if (t < 1023) {
            const float4* kp = (const float4*)(kc + cbase + (size_t)t * 64);
            const float4* qp = (const float4*)q;
#pragma unroll
            for (int i = 0; i < 16; i++) {
                float4 kv = __ldg(kp + i), qv = qp[i];
                a += kv.x * qv.x + kv.y * qv.y + kv.z * qv.z + kv.w * qv.w;
            }
        } else {
            for (int j = 0; j < 64; j++) a += q[j] * KT[(h * 64 + j) * 16 + b];
        }
        SCs[(size_t)(b * 16 + h) * 1024 + t] = a * SCALE_F;
    }
}

// in-place softmax on rows of 1024: grid (16,16), 256 thr
__global__ void sa_softmax(float* __restrict__ SCs) {
    const int b = blockIdx.x, h = blockIdx.y, tid = threadIdx.x;
    float* p = SCs + (size_t)(b * 16 + h) * 1024;
    __shared__ float red[256];
    float v[4], m = -1e30f;
#pragma unroll
    for (int i = 0; i < 4; i++) { v[i] = p[tid + i * 256]; m = fmaxf(m, v[i]); }
    red[tid] = m; __syncthreads();
    for (int st = 128; st > 0; st >>= 1) { if (tid < st) red[tid] = fmaxf(red[tid], red[tid + st]); __syncthreads(); }
    m = red[0]; __syncthreads();
    float ssum = 0.f;
#pragma unroll
    for (int i = 0; i < 4; i++) { v[i] = __expf(v[i] - m); ssum += v[i]; }
    red[tid] = ssum; __syncthreads();
    for (int st = 128; st > 0; st >>= 1) { if (tid < st) red[tid] += red[tid + st]; __syncthreads(); }
    const float inv = 1.f / red[0];
#pragma unroll
    for (int i = 0; i < 4; i++) p[tid + i * 256] = v[i] * inv;
}

// V partials: grid (16 b, 16 h, 8 tc), 64 thr. VP[((b*16+h)*8+tc)*64+j]
__global__ void sa_v(const float* __restrict__ SCs, const float* __restrict__ VT,
                     const float* __restrict__ vc, float* __restrict__ VP) {
    const int b = blockIdx.x, h = blockIdx.y, tc = blockIdx.z, j = threadIdx.x;
    const size_t cbase = (size_t)(b * 16 + h) * 1023 * 64;
    const float* p = SCs + (size_t)(b * 16 + h) * 1024;
    float acc = 0.f;
    const int t0 = tc * 128;
#pragma unroll 8
    for (int i = 0; i < 128; i++) {
        const int t = t0 + i;
        float v = (t < 1023) ? __ldg(vc + cbase + (size_t)t * 64 + j)
                             : VT[(h * 64 + j) * 16 + b];
        acc += p[t] * v;
    }
    VP[(size_t)((b * 16 + h) * 8 + tc) * 64 + j] = acc;
}

// combine V partials -> ATT
__global__ void sa_comb(const float* __restrict__ VP, float* __restrict__ ATT) {
    const int b = blockIdx.x, h = blockIdx.y, j = threadIdx.x;
    float s = 0.f;
#pragma unroll
    for (int c = 0; c < 8; c++) s += VP[(size_t)((b * 16 + h) * 8 + c) * 64 + j];
    ATT[(h * 64 + j) * 16 + b] = s;
}

__global__ void lnk(const float* __restrict__ T, const float* __restrict__ g,
                    const float* __restrict__ be, float* __restrict__ XT) {
    const int b = blockIdx.x, tid = threadIdx.x;
    __shared__ float red[256];
    float s = 0.f;
    for (int o = tid; o < 1024; o += 256) s += T[o * 16 + b];
    red[tid] = s; __syncthreads();
    for (int st = 128; st > 0; st >>= 1) { if (tid < st) red[tid] += red[tid + st]; __syncthreads(); }
    const float mean = red[0] * (1.f / 1024.f);
    __syncthreads();
    float v = 0.f;
    for (int o = tid; o < 1024; o += 256) { float d = T[o * 16 + b] - mean; v += d * d; }
    red[tid] = v; __syncthreads();
    for (int st = 128; st > 0; st >>= 1) { if (tid < st) red[tid] += red[tid + st]; __syncthreads(); }
    const float rstd = rsqrtf(red[0] * (1.f / 1024.f) + EPS_F);
    for (int o = tid; o < 1024; o += 256)
        XT[o * 16 + b] = (T[o * 16 + b] - mean) * rstd * g[o] + be[o];
}

// U[(b*16+h)*1024+d] = sum_j Wk[d*1024 + h*64+j] * QC[(h*64+j)*16+b]
__global__ void ukern(const float* __restrict__ Wk, const float* __restrict__ QC,
                      float* __restrict__ U) {
    const int d = blockIdx.x, tid = threadIdx.x;
    __shared__ float w[1024];
    for (int i = tid; i < 1024; i += 256) w[i] = __ldg(&Wk[(size_t)d * 1024 + i]);
    __syncthreads();
    const int b = tid & 15, h = tid >> 4;
    float a = 0.f;
#pragma unroll 8
    for (int j = 0; j < 64; j++) a += w[h * 64 + j] * QC[(h * 64 + j) * 16 + b];
    U[(size_t)(b * 16 + h) * 1024 + d] = a;
}

// SCX[dh*262144 + (b*16+h)*1024+s] = partial dot over 512 d
__global__ void xscores(const float* __restrict__ enc, const float* __restrict__ U,
                        float* __restrict__ SCX) {
    const int b = blockIdx.x, s = blockIdx.y * 128 + threadIdx.x, dh = blockIdx.z;
    __shared__ float ush[16][512];
    float acc[16];
#pragma unroll
    for (int h = 0; h < 16; h++) acc[h] = 0.f;
    for (int i = threadIdx.x; i < 8192; i += 128)
        ush[i >> 9][i & 511] = __ldg(&U[(size_t)(b * 16 + (i >> 9)) * 1024 + dh * 512 + (i & 511)]);
    __syncthreads();
    const float* ep = enc + (size_t)(b * 1024 + s) * 1024 + dh * 512;
#pragma unroll 4
    for (int d = 0; d < 512; d += 4) {
        float4 e = __ldg((const float4*)(ep + d));
#pragma unroll
        for (int h = 0; h < 16; h++) {
            float4 u4 = *(const float4*)&ush[h][d];
            acc[h] += e.x * u4.x + e.y * u4.y + e.z * u4.z + e.w * u4.w;
        }
    }
#pragma unroll
    for (int h = 0; h < 16; h++)
        SCX[(size_t)dh * 262144 + (size_t)(b * 16 + h) * 1024 + s] = acc[h];
}

// sums 2 d-half partials, softmax, writes AT[(b*1024+s)*16+h]
__global__ void xsoftmax(const float* __restrict__ SCX, float* __restrict__ AT) {
    const int b = blockIdx.x, h = blockIdx.y, tid = threadIdx.x;
    const float* p0 = SCX + (size_t)(b * 16 + h) * 1024;
    const float* p1 = p0 + 262144;
    __shared__ float red[256];
    float v[4], m = -1e30f;
#pragma unroll
    for (int i = 0; i < 4; i++) {
        const int s = tid + i * 256;
        v[i] = SCALE_F * (p0[s] + p1[s]);
        m = fmaxf(m, v[i]);
    }
    red[tid] = m; __syncthreads();
    for (int st = 128; st > 0; st >>= 1) { if (tid < st) red[tid] = fmaxf(red[tid], red[tid + st]); __syncthreads(); }
    m = red[0]; __syncthreads();
    float ssum = 0.f;
#pragma unroll
    for (int i = 0; i < 4; i++) { v[i] = __expf(v[i] - m); ssum += v[i]; }
    red[tid] = ssum; __syncthreads();
    for (int st = 128; st > 0; st >>= 1) { if (tid < st) red[tid] += red[tid + st]; __syncthreads(); }
    const float inv = 1.f / red[0];
#pragma unroll
    for (int i = 0; i < 4; i++) AT[(size_t)(b * 1024 + tid + i * 256) * 16 + h] = v[i] * inv;
}

// ctx partials: grid (16 b, 4 dt, 4 sz), 256 thr. CT[sz*262144 + (h*1024+d)*16+b]
__global__ void xctx(const float* __restrict__ enc, const float* __restrict__ AT,
                     float* __restrict__ CT) {
    const int b = blockIdx.x, d = blockIdx.y * 256 + threadIdx.x, sz = blockIdx.z;
    const int s0 = sz * 256;
    float acc[16];
#pragma unroll
    for (int h = 0; h < 16; h++) acc[h] = 0.f;
    const float* ep = enc + (size_t)(b * 1024 + s0) * 1024 + d;
    const float4* ap = (const float4*)(AT + (size_t)(b * 1024 + s0) * 16);
#pragma unroll 4
    for (int s = 0; s < 256; s++) {
        float e = __ldg(ep); ep += 1024;
        float4 p0 = __ldg(ap), p1 = __ldg(ap + 1), p2 = __ldg(ap + 2), p3 = __ldg(ap + 3); ap += 4;
        acc[0] += e * p0.x; acc[1] += e * p0.y; acc[2] += e * p0.z; acc[3] += e * p0.w;
        acc[4] += e * p1.x; acc[5] += e * p1.y; acc[6] += e * p1.z; acc[7] += e * p1.w;
        acc[8] += e * p2.x; acc[9] += e * p2.y; acc[10] += e * p2.z; acc[11] += e * p2.w;
        acc[12] += e * p3.x; acc[13] += e * p3.y; acc[14] += e * p3.z; acc[15] += e * p3.w;
    }
#pragma unroll
    for (int h = 0; h < 16; h++)
        CT[(size_t)sz * 262144 + (size_t)(h * 1024 + d) * 16 + b] = acc[h];
}

__global__ void logits_k(const float* __restrict__ XT, const float* __restrict__ W,
                         const float* __restrict__ bias, float* __restrict__ out) {
    const int v = blockIdx.x, tid = threadIdx.x;
    float acc[16];
#pragma unroll
    for (int b = 0; b < 16; b++) acc[b] = 0.f;
    for (int k = tid; k < 1024; k += 256) {
        float w = __ldg(&W[k * 20 + v]);
        const float4* a4 = (const float4*)(XT + k * 16);
        float4 a0 = a4[0], a1 = a4[1], a2 = a4[2], a3 = a4[3];
        acc[0] += w * a0.x; acc[1] += w * a0.y; acc[2] += w * a0.z; acc[3] += w * a0.w;
        acc[4] += w * a1.x; acc[5] += w * a1.y; acc[6] += w * a1.z; acc[7] += w * a1.w;
        acc[8] += w * a2.x; acc[9] += w * a2.y; acc[10] += w * a2.z; acc[11] += w * a2.w;
        acc[12] += w * a3.x; acc[13] += w * a3.y; acc[14] += w * a3.z; acc[15] += w * a3.w;
    }
    __shared__ float sh[256][17];
#pragma unroll
    for (int b = 0; b < 16; b++) sh[tid][b] = acc[b];
    __syncthreads();
    for (int st = 128; st > 0; st >>= 1) {
        if (tid < st)
#pragma unroll
            for (int b = 0; b < 16; b++) sh[tid][b] += sh[tid + st][b];
        __syncthreads();
    }
    if (tid < 16) out[tid * 20 + v] = sh[0][tid] + bias[v];
}

static inline void gemv(const float* A, int aparts, int astride, const float* W,
                        const float* bias, const float* resid, float* P,
                        float* outT, int N, int K, int ksplit, int hs, int relu) {
    gemv_part2<<<dim3(N / 128, ksplit, 1), 256>>>(A, aparts, astride, W, W, W, P, N, K, ksplit, hs);
    greduce<<<N * 16 / 256, 256>>>(P, bias, resid, outT, N, ksplit, relu);
}

extern "C" void kernel_launch(void* const* d_in, const int* in_sizes, int n_in,
                              void* d_out, int out_size) {
    const float* x    = (const float*)d_in[0];
    const float* enc  = (const float*)d_in[1];
    const float* kc   = (const float*)d_in[2];
    const float* vc   = (const float*)d_in[3];
    const float* W[32]; for (int i = 4; i < 32; i++) W[i] = (const float*)d_in[i];
    void* bp; cudaGetSymbolAddress(&bp, g_buf);
    float* B = (float*)bp;
    float *XT = B + O_XT, *QT = B + O_QT, *KT = B + O_KT, *VT = B + O_VT;
    float *ATT = B + O_ATT, *TMP = B + O_TMP, *QC = B + O_QC, *CATT = B + O_CATT;
    float *HID = B + O_HID, *U = B + O_U, *SC = B + O_SC, *AT = B + O_AT;
    float *CT = B + O_CT, *P = B + O_P;

    tin<<<64, 256>>>(x, XT);
    for (int l = 0; l < 3; l++) {
        const size_t wo = (size_t)l * 1048576, bo = (size_t)l * 1024;
        const size_t co = (size_t)l * 16 * 16 * 1023 * 64;
        // fused Q,K,V projections: one launch, 768 blocks
        gemv_part2<<<dim3(8, 32, 3), 256>>>(XT, 1, 0, W[4] + wo, W[6] + wo, W[8] + wo,
                                            P, 1024, 1024, 32, 0);
        greduce3<<<dim3(64, 3), 256>>>(P, W[5] + bo, W[7] + bo, W[9] + bo,
                                       QT, KT, VT, 1024, 32);
        sa_scores<<<dim3(16, 16, 4), 128>>>(QT, KT, kc + co, SC);
        sa_softmax<<<dim3(16, 16), 256>>>(SC);
        sa_v<<<dim3(16, 16, 8), 64>>>(SC, VT, vc + co, AT);
        sa_comb<<<dim3(16, 16), 64>>>(AT, ATT);
        gemv(ATT, 1, 0, W[10] + wo, W[11] + bo, XT, P, TMP, 1024, 1024, 32, 0, 0);
        lnk<<<16, 256>>>(TMP, W[24] + bo, W[25] + bo, XT);
        gemv(XT, 1, 0, W[12] + wo, W[13] + bo, nullptr, P, QC, 1024, 1024, 32, 0, 0);
        ukern<<<1024, 256>>>(W[14] + wo, QC, U);
        xscores<<<dim3(16, 8, 2), 128>>>(enc, U, SC);
        xsoftmax<<<dim3(16, 16), 256>>>(SC, AT);
        xctx<<<dim3(16, 4, 4), 256>>>(enc, AT, CT);
        gemv(CT, 4, 262144, W[16] + wo, W[17] + bo, nullptr, P, CATT, 1024, 1024, 32, 1024, 0);
        gemv(CATT, 1, 0, W[18] + wo, W[19] + bo, XT, P, TMP, 1024, 1024, 32, 0, 0);
        lnk<<<16, 256>>>(TMP, W[26] + bo, W[27] + bo, XT);
        gemv(XT, 1, 0, W[20] + (size_t)l * 4194304, W[21] + (size_t)l * 4096,
             nullptr, P, HID, 4096, 1024, 8, 0, 1);
        gemv(HID, 1, 0, W[22] + (size_t)l * 4194304, W[23] + bo, XT, P, TMP,
             1024, 4096, 32, 0, 0);
        lnk<<<16, 256>>>(TMP, W[28] + bo, W[29] + bo, XT);
    }
    logits_k<<<20, 256>>>(XT, W[30], W[31], (float*)d_out);
}